// round 11
// baseline (speedup 1.0000x reference)
#include <cuda_runtime.h>

// Problem constants
#define PP 12
#define BB 4
#define KSTEP 12
#define TE_DEPTH 168
#define NUM_CELLS 1024   // 32*32
#define PQ 24            // P + Q

// Output layout (tuple flattened, row-major each):
//  Y       (B,1,H,W,1)       4096   @ 0
//  x       (B,P,H,W,1)      49152   @ 4096
//  trans   (B,P,H,W,8,1)   393216   @ 53248
//  restart (B,P,H,W,1)      49152   @ 446464
//  results (B,P,H,W,1,13)  638976   @ 495616
#define OFF_Y    0
#define OFF_X    4096
#define OFF_T    53248
#define OFF_R    446464
#define OFF_RES  495616

// Dynamic smem layout (floats):
//  tp    @ 0      : 8 planes of 34x34 (9248)
//  xs    @ 9248   : 2 buffers of 34x34 (2312)   [tp+xs zeroed together: 11560]
//  stage @ 11560  : 352*13 this-CTA's-third results staging (4576)
//  wte_s @ 16136  : Wt[0:168] rows (1344)
//  wr_s  @ 17480  : Wr[0:168] (168)
//  wb_s  @ 17648  : Wb[0:168] (168)
#define TP_OFF    0
#define XS_OFF    9248
#define STG_OFF   11560
#define WTE_OFF   16136
#define WR_OFF    17480
#define WB_OFF    17648
#define SMEM_FLOATS 17816   // 71264 B

// Three CTAs per (b,p) plane: all compute the full plane (duplicated, cheap),
// each stores only its third of every output. grid = 48*3 = 144 (~1 CTA/SM).
// Thirds are warp-aligned: part 0 -> cells [0,352), part 1 -> [352,704),
// part 2 -> [704,1024) (11/11/10 warps).

__global__ __launch_bounds__(1024, 1) void rwr_kernel(
    const float* __restrict__ X,
    const int*   __restrict__ TE,
    const float* __restrict__ Wt,   // (1192, 8)
    const float* __restrict__ Wr,   // (1192, 1)
    const float* __restrict__ Wb,   // (1192, 1)
    float*       __restrict__ out)
{
    extern __shared__ __align__(16) float sm[];
    float* tp    = sm + TP_OFF;     // tp[d*1156 + r*34 + c]
    float* xs    = sm + XS_OFF;     // xs[buf*1156 + r*34 + c]
    float* stage = sm + STG_OFF;
    float* wte_s = sm + WTE_OFF;
    float* wr_s  = sm + WR_OFF;
    float* wb_s  = sm + WB_OFF;

    const int bp   = blockIdx.x / 3;    // 0..47
    const int part = blockIdx.x % 3;    // which third of outputs this CTA owns
    const int b    = bp / PP;
    const int p    = bp % PP;
    const int cell = threadIdx.x;       // 0..1023
    const int h    = cell >> 5;
    const int w    = cell & 31;

    const int base  = part * 352;                     // 0 / 352 / 704
    const int ncell = (part == 2) ? 320 : 352;
    const bool mine = (cell >= base) && (cell < base + ncell);   // warp-uniform

    // ---- issue ALL independent global loads at cycle 0 (max MLP) ----
    const float x0 = X[bp * NUM_CELLS + cell];
    const int te_day  = TE[(b * PQ + p) * 2 + 0];
    const int te_hour = TE[(b * PQ + p) * 2 + 1];
    const int cr = TE_DEPTH + cell;

    const float4* wc4 = reinterpret_cast<const float4*>(Wt + (size_t)cr * 8);
    const float4 wc_lo = wc4[0];
    const float4 wc_hi = wc4[1];
    const float wr_c = Wr[cr];
    const float wb_c = Wb[cr];

    // speculative te-block load -> smem (independent of TE value):
    //  Wt[0:168] = 336 float4; Wr[0:168] = 42 float4; Wb[0:168] = 42 float4
    if (cell < 420) {
        float4 v;
        if (cell < 336)      v = reinterpret_cast<const float4*>(Wt)[cell];
        else if (cell < 378) v = reinterpret_cast<const float4*>(Wr)[cell - 336];
        else                 v = reinterpret_cast<const float4*>(Wb)[cell - 378];
        float4* dst;
        if (cell < 336)      dst = reinterpret_cast<float4*>(wte_s) + cell;
        else if (cell < 378) dst = reinterpret_cast<float4*>(wr_s) + (cell - 336);
        else                 dst = reinterpret_cast<float4*>(wb_s) + (cell - 378);
        *dst = v;
    }

    // ---- full float4 zero of tp + xs (2890 float4); interior refilled after BAR#1 ----
    {
        float4* z4 = reinterpret_cast<float4*>(sm);
        const float4 zv = make_float4(0.f, 0.f, 0.f, 0.f);
        z4[cell] = zv;
        z4[cell + 1024] = zv;
        if (cell < 842) z4[cell + 2048] = zv;
    }

    __syncthreads();   // BAR#1: te-block resident + zero done

    // ---- read te row from smem (no second DRAM trip) ----
    const int te = te_day * 24 + te_hour;            // < 168
    const float4 wt_lo = reinterpret_cast<const float4*>(wte_s)[te * 2];
    const float4 wt_hi = reinterpret_cast<const float4*>(wte_s)[te * 2 + 1];
    const float wr_te = wr_s[te];
    const float wb_te = wb_s[te];

    // ---- softmax over 8 dirs (fast math; logits tiny, skip max-sub) ----
    float e[8], s = 0.f;
    e[0] = __expf(wt_lo.x + wc_lo.x);  e[1] = __expf(wt_lo.y + wc_lo.y);
    e[2] = __expf(wt_lo.z + wc_lo.z);  e[3] = __expf(wt_lo.w + wc_lo.w);
    e[4] = __expf(wt_hi.x + wc_hi.x);  e[5] = __expf(wt_hi.y + wc_hi.y);
    e[6] = __expf(wt_hi.z + wc_hi.z);  e[7] = __expf(wt_hi.w + wc_hi.w);
    #pragma unroll
    for (int d = 0; d < 8; d++) s += e[d];
    const float inv_s = __fdividef(1.0f, s);
    float tpv[8];
    #pragma unroll
    for (int d = 0; d < 8; d++) tpv[d] = e[d] * inv_s;

    const float rz = wr_te + wr_c;
    const float restart = __fdividef(1.0f, 1.0f + __expf(-rz));
    const float one_m_r = 1.0f - restart;
    const float bias = (wb_te + wb_c) * x0;

    // ---- static outputs: ONLY this CTA's third ----
    if (mine) {
        float4* t4 = reinterpret_cast<float4*>(out + OFF_T + (size_t)(bp * NUM_CELLS + cell) * 8);
        t4[0] = make_float4(tpv[0], tpv[1], tpv[2], tpv[3]);
        t4[1] = make_float4(tpv[4], tpv[5], tpv[6], tpv[7]);
        out[OFF_R + bp * NUM_CELLS + cell] = restart;
    }

    // ---- fill tp interior + x0 into xs buf0 + stage[0] (all pre-BAR#2) ----
    const int ctr = (h + 1) * 34 + (w + 1);
    #pragma unroll
    for (int d = 0; d < 8; d++) tp[d * 1156 + ctr] = tpv[d];

    float* const xc0 = xs + ctr;          // buf 0 center
    float* const xc1 = xs + 1156 + ctr;   // buf 1 center
    float* sp = stage + (cell - base) * 13;   // per-cell stage pointer (local third)

    xc0[0] = x0;
    if (mine) sp[0] = x0;

    __syncthreads();   // BAR#2: tp + xs buf0 ready

    // DIRS d: 0:(-1,-1) 1:(-1,0) 2:(-1,1) 3:(0,-1) 4:(0,1) 5:(1,-1) 6:(1,0) 7:(1,1)
    float w_in[8];
    {
        const float* tpc = tp + ctr;
        w_in[0] = tpc[0 * 1156 - 35];
        w_in[1] = tpc[1 * 1156 - 34];
        w_in[2] = tpc[2 * 1156 - 33];
        w_in[3] = tpc[3 * 1156 -  1];
        w_in[4] = tpc[4 * 1156 +  1];
        w_in[5] = tpc[5 * 1156 + 33];
        w_in[6] = tpc[6 * 1156 + 34];
        w_in[7] = tpc[7 * 1156 + 35];
    }

    // ---- peeled iteration 0 (reads buf0, covered by BAR#2) ----
    float x;
    {
        float a0 = xc0[-35] * w_in[0];
        float a1 = xc0[-34] * w_in[1];
        float a2 = xc0[-33] * w_in[2];
        float a3 = xc0[ -1] * w_in[3];
        a0 = fmaf(xc0[  1], w_in[4], a0);
        a1 = fmaf(xc0[ 33], w_in[5], a1);
        a2 = fmaf(xc0[ 34], w_in[6], a2);
        a3 = fmaf(xc0[ 35], w_in[7], a3);
        const float xt = (a0 + a1) + (a2 + a3);
        x = fmaf(one_m_r, xt, fmaf(restart, x0, bias));
        if (mine) sp[1] = x;
    }

    // ---- iterations 1..11: store -> BAR -> stencil ----
    #pragma unroll
    for (int k = 1; k < KSTEP; k++) {
        float* const xb = (k & 1) ? xc1 : xc0;
        xb[0] = x;
        __syncthreads();
        float a0 = xb[-35] * w_in[0];
        float a1 = xb[-34] * w_in[1];
        float a2 = xb[-33] * w_in[2];
        float a3 = xb[ -1] * w_in[3];
        a0 = fmaf(xb[  1], w_in[4], a0);
        a1 = fmaf(xb[ 33], w_in[5], a1);
        a2 = fmaf(xb[ 34], w_in[6], a2);
        a3 = fmaf(xb[ 35], w_in[7], a3);
        const float xt = (a0 + a1) + (a2 + a3);
        x = fmaf(one_m_r, xt, fmaf(restart, x, bias));
        if (mine) sp[k + 1] = x;
    }

    // final state x + Y: only this CTA's third
    if (mine) {
        out[OFF_X + bp * NUM_CELLS + cell] = x;
        if (p == PP - 1)
            out[OFF_Y + b * NUM_CELLS + cell] = x;
    }

    // ---- one barrier, then dump ONLY this third (1144 / 1144 / 1040 float4) ----
    __syncthreads();
    const int n4 = (ncell * 13) >> 2;          // 1144 or 1040
    const float4* s4 = reinterpret_cast<const float4*>(stage);
    float4* o4 = reinterpret_cast<float4*>(out + OFF_RES + (size_t)bp * (NUM_CELLS * 13))
                 + ((base * 13) >> 2);
    o4[cell] = s4[cell];                       // cell < 1024 <= n4? (1024 < 1144 ok; part2: 1024<1040 ok)
    if (cell < n4 - 1024) o4[cell + 1024] = s4[cell + 1024];
}

extern "C" void kernel_launch(void* const* d_in, const int* in_sizes, int n_in,
                              void* d_out, int out_size) {
    const float* X  = (const float*)d_in[0];
    const int*   TE = (const int*)d_in[1];
    const float* Wt = (const float*)d_in[2];
    const float* Wr = (const float*)d_in[3];
    const float* Wb = (const float*)d_in[4];
    float* out = (float*)d_out;
    const int smem_bytes = SMEM_FLOATS * 4;   // 71264 B
    cudaFuncSetAttribute(rwr_kernel, cudaFuncAttributeMaxDynamicSharedMemorySize, smem_bytes);
    rwr_kernel<<<BB * PP * 3, 1024, smem_bytes>>>(X, TE, Wt, Wr, Wb, out);
}

// round 12
// speedup vs baseline: 1.2353x; 1.2353x over previous
#include <cuda_runtime.h>

// Problem constants
#define PP 12
#define BB 4
#define KSTEP 12
#define TE_DEPTH 168
#define NUM_CELLS 1024   // 32*32
#define PQ 24            // P + Q

// Output layout (tuple flattened, row-major each):
//  Y       (B,1,H,W,1)       4096   @ 0
//  x       (B,P,H,W,1)      49152   @ 4096
//  trans   (B,P,H,W,8,1)   393216   @ 53248
//  restart (B,P,H,W,1)      49152   @ 446464
//  results (B,P,H,W,1,13)  638976   @ 495616
#define OFF_Y    0
#define OFF_X    4096
#define OFF_T    53248
#define OFF_R    446464
#define OFF_RES  495616

// Dynamic smem layout (floats):
//  tp    @ 0      : 8 planes of 34x34 (9248)
//  xs    @ 9248   : 2 buffers of 34x34 (2312)   [tp+xs zeroed together: 11560]
//  stage @ 11560  : 352*13 this-CTA's-third results staging (4576)
//  wte_s @ 16136  : Wt[0:168] rows (1344)
//  wr_s  @ 17480  : Wr[0:168] (168)
//  wb_s  @ 17648  : Wb[0:168] (168)
#define TP_OFF    0
#define XS_OFF    9248
#define STG_OFF   11560
#define WTE_OFF   16136
#define WR_OFF    17480
#define WB_OFF    17648
#define SMEM_FLOATS 17816   // 71264 B

// Three CTAs per (b,p) plane: all compute the full plane (duplicated, cheap),
// each stores only its third of every output. grid = 48*3 = 144 (~1 CTA/SM).
// Thirds are warp-aligned: part 0 -> cells [0,352), part 1 -> [352,704),
// part 2 -> [704,1024) (11/11/10 warps).

__global__ __launch_bounds__(1024, 1) void rwr_kernel(
    const float* __restrict__ X,
    const int*   __restrict__ TE,
    const float* __restrict__ Wt,   // (1192, 8)
    const float* __restrict__ Wr,   // (1192, 1)
    const float* __restrict__ Wb,   // (1192, 1)
    float*       __restrict__ out)
{
    extern __shared__ __align__(16) float sm[];
    float* tp    = sm + TP_OFF;     // tp[d*1156 + r*34 + c]
    float* xs    = sm + XS_OFF;     // xs[buf*1156 + r*34 + c]
    float* stage = sm + STG_OFF;
    float* wte_s = sm + WTE_OFF;
    float* wr_s  = sm + WR_OFF;
    float* wb_s  = sm + WB_OFF;

    const int bp   = blockIdx.x / 3;    // 0..47
    const int part = blockIdx.x % 3;    // which third of outputs this CTA owns
    const int b    = bp / PP;
    const int p    = bp % PP;
    const int cell = threadIdx.x;       // 0..1023
    const int h    = cell >> 5;
    const int w    = cell & 31;

    const int base  = part * 352;                     // 0 / 352 / 704
    const int ncell = (part == 2) ? 320 : 352;
    const bool mine = (cell >= base) && (cell < base + ncell);   // warp-uniform

    // ---- issue ALL independent global loads at cycle 0 (max MLP) ----
    const float x0 = X[bp * NUM_CELLS + cell];
    const int te_day  = TE[(b * PQ + p) * 2 + 0];
    const int te_hour = TE[(b * PQ + p) * 2 + 1];
    const int cr = TE_DEPTH + cell;

    const float4* wc4 = reinterpret_cast<const float4*>(Wt + (size_t)cr * 8);
    const float4 wc_lo = wc4[0];
    const float4 wc_hi = wc4[1];
    const float wr_c = Wr[cr];
    const float wb_c = Wb[cr];

    // speculative te-block load -> smem (independent of TE value):
    //  Wt[0:168] = 336 float4; Wr[0:168] = 42 float4; Wb[0:168] = 42 float4
    if (cell < 420) {
        float4 v;
        if (cell < 336)      v = reinterpret_cast<const float4*>(Wt)[cell];
        else if (cell < 378) v = reinterpret_cast<const float4*>(Wr)[cell - 336];
        else                 v = reinterpret_cast<const float4*>(Wb)[cell - 378];
        float4* dst;
        if (cell < 336)      dst = reinterpret_cast<float4*>(wte_s) + cell;
        else if (cell < 378) dst = reinterpret_cast<float4*>(wr_s) + (cell - 336);
        else                 dst = reinterpret_cast<float4*>(wb_s) + (cell - 378);
        *dst = v;
    }

    // ---- full float4 zero of tp + xs (2890 float4); interior refilled after BAR#1 ----
    {
        float4* z4 = reinterpret_cast<float4*>(sm);
        const float4 zv = make_float4(0.f, 0.f, 0.f, 0.f);
        z4[cell] = zv;
        z4[cell + 1024] = zv;
        if (cell < 842) z4[cell + 2048] = zv;
    }

    __syncthreads();   // BAR#1: te-block resident + zero done

    // ---- read te row from smem (no second DRAM trip) ----
    const int te = te_day * 24 + te_hour;            // < 168
    const float4 wt_lo = reinterpret_cast<const float4*>(wte_s)[te * 2];
    const float4 wt_hi = reinterpret_cast<const float4*>(wte_s)[te * 2 + 1];
    const float wr_te = wr_s[te];
    const float wb_te = wb_s[te];

    // ---- softmax over 8 dirs (fast math; logits tiny, skip max-sub) ----
    float e[8], s = 0.f;
    e[0] = __expf(wt_lo.x + wc_lo.x);  e[1] = __expf(wt_lo.y + wc_lo.y);
    e[2] = __expf(wt_lo.z + wc_lo.z);  e[3] = __expf(wt_lo.w + wc_lo.w);
    e[4] = __expf(wt_hi.x + wc_hi.x);  e[5] = __expf(wt_hi.y + wc_hi.y);
    e[6] = __expf(wt_hi.z + wc_hi.z);  e[7] = __expf(wt_hi.w + wc_hi.w);
    #pragma unroll
    for (int d = 0; d < 8; d++) s += e[d];
    const float inv_s = __fdividef(1.0f, s);
    float tpv[8];
    #pragma unroll
    for (int d = 0; d < 8; d++) tpv[d] = e[d] * inv_s;

    const float rz = wr_te + wr_c;
    const float restart = __fdividef(1.0f, 1.0f + __expf(-rz));
    const float one_m_r = 1.0f - restart;
    const float bias = (wb_te + wb_c) * x0;

    // ---- static outputs: ONLY this CTA's third ----
    if (mine) {
        float4* t4 = reinterpret_cast<float4*>(out + OFF_T + (size_t)(bp * NUM_CELLS + cell) * 8);
        t4[0] = make_float4(tpv[0], tpv[1], tpv[2], tpv[3]);
        t4[1] = make_float4(tpv[4], tpv[5], tpv[6], tpv[7]);
        out[OFF_R + bp * NUM_CELLS + cell] = restart;
    }

    // ---- fill tp interior + x0 into xs buf0 + stage[0] (all pre-BAR#2) ----
    const int ctr = (h + 1) * 34 + (w + 1);
    #pragma unroll
    for (int d = 0; d < 8; d++) tp[d * 1156 + ctr] = tpv[d];

    float* const xc0 = xs + ctr;          // buf 0 center
    float* const xc1 = xs + 1156 + ctr;   // buf 1 center
    float* sp = stage + (cell - base) * 13;   // per-cell stage pointer (local third)

    xc0[0] = x0;
    if (mine) sp[0] = x0;

    __syncthreads();   // BAR#2: tp + xs buf0 ready

    // DIRS d: 0:(-1,-1) 1:(-1,0) 2:(-1,1) 3:(0,-1) 4:(0,1) 5:(1,-1) 6:(1,0) 7:(1,1)
    float w_in[8];
    {
        const float* tpc = tp + ctr;
        w_in[0] = tpc[0 * 1156 - 35];
        w_in[1] = tpc[1 * 1156 - 34];
        w_in[2] = tpc[2 * 1156 - 33];
        w_in[3] = tpc[3 * 1156 -  1];
        w_in[4] = tpc[4 * 1156 +  1];
        w_in[5] = tpc[5 * 1156 + 33];
        w_in[6] = tpc[6 * 1156 + 34];
        w_in[7] = tpc[7 * 1156 + 35];
    }

    // ---- peeled iteration 0 (reads buf0, covered by BAR#2) ----
    float x;
    {
        float a0 = xc0[-35] * w_in[0];
        float a1 = xc0[-34] * w_in[1];
        float a2 = xc0[-33] * w_in[2];
        float a3 = xc0[ -1] * w_in[3];
        a0 = fmaf(xc0[  1], w_in[4], a0);
        a1 = fmaf(xc0[ 33], w_in[5], a1);
        a2 = fmaf(xc0[ 34], w_in[6], a2);
        a3 = fmaf(xc0[ 35], w_in[7], a3);
        const float xt = (a0 + a1) + (a2 + a3);
        x = fmaf(one_m_r, xt, fmaf(restart, x0, bias));
        if (mine) sp[1] = x;
    }

    // ---- iterations 1..11: store -> BAR -> stencil ----
    #pragma unroll
    for (int k = 1; k < KSTEP; k++) {
        float* const xb = (k & 1) ? xc1 : xc0;
        xb[0] = x;
        __syncthreads();
        float a0 = xb[-35] * w_in[0];
        float a1 = xb[-34] * w_in[1];
        float a2 = xb[-33] * w_in[2];
        float a3 = xb[ -1] * w_in[3];
        a0 = fmaf(xb[  1], w_in[4], a0);
        a1 = fmaf(xb[ 33], w_in[5], a1);
        a2 = fmaf(xb[ 34], w_in[6], a2);
        a3 = fmaf(xb[ 35], w_in[7], a3);
        const float xt = (a0 + a1) + (a2 + a3);
        x = fmaf(one_m_r, xt, fmaf(restart, x, bias));
        if (mine) sp[k + 1] = x;
    }

    // final state x + Y: only this CTA's third
    if (mine) {
        out[OFF_X + bp * NUM_CELLS + cell] = x;
        if (p == PP - 1)
            out[OFF_Y + b * NUM_CELLS + cell] = x;
    }

    // ---- one barrier, then dump ONLY this third (1144 / 1144 / 1040 float4) ----
    __syncthreads();
    const int n4 = (ncell * 13) >> 2;          // 1144 or 1040
    const float4* s4 = reinterpret_cast<const float4*>(stage);
    float4* o4 = reinterpret_cast<float4*>(out + OFF_RES + (size_t)bp * (NUM_CELLS * 13))
                 + ((base * 13) >> 2);
    o4[cell] = s4[cell];                       // cell < 1024 <= n4? (1024 < 1144 ok; part2: 1024<1040 ok)
    if (cell < n4 - 1024) o4[cell + 1024] = s4[cell + 1024];
}

extern "C" void kernel_launch(void* const* d_in, const int* in_sizes, int n_in,
                              void* d_out, int out_size) {
    const float* X  = (const float*)d_in[0];
    const int*   TE = (const int*)d_in[1];
    const float* Wt = (const float*)d_in[2];
    const float* Wr = (const float*)d_in[3];
    const float* Wb = (const float*)d_in[4];
    float* out = (float*)d_out;
    const int smem_bytes = SMEM_FLOATS * 4;   // 71264 B
    cudaFuncSetAttribute(rwr_kernel, cudaFuncAttributeMaxDynamicSharedMemorySize, smem_bytes);
    rwr_kernel<<<BB * PP * 3, 1024, smem_bytes>>>(X, TE, Wt, Wr, Wb, out);
}

// round 13
// speedup vs baseline: 1.2444x; 1.0074x over previous
#include <cuda_runtime.h>

// Problem constants
#define PP 12
#define BB 4
#define KSTEP 12
#define TE_DEPTH 168
#define NUM_CELLS 1024   // 32*32
#define PQ 24            // P + Q

// Output layout (tuple flattened, row-major each):
//  Y       (B,1,H,W,1)       4096   @ 0
//  x       (B,P,H,W,1)      49152   @ 4096
//  trans   (B,P,H,W,8,1)   393216   @ 53248
//  restart (B,P,H,W,1)      49152   @ 446464
//  results (B,P,H,W,1,13)  638976   @ 495616
#define OFF_Y    0
#define OFF_X    4096
#define OFF_T    53248
#define OFF_R    446464
#define OFF_RES  495616

// Dynamic smem layout (floats):
//  tp    @ 0      : 8 planes of 34x34 (9248)
//  xs    @ 9248   : 2 buffers of 34x34 (2312)   [tp+xs zeroed together: 11560]
//  stage @ 11560  : 352*13 this-CTA's-third results staging (4576)
//  wte_s @ 16136  : Wt[0:168] rows (1344)
//  wr_s  @ 17480  : Wr[0:168] (168)
//  wb_s  @ 17648  : Wb[0:168] (168)
#define TP_OFF    0
#define XS_OFF    9248
#define STG_OFF   11560
#define WTE_OFF   16136
#define WR_OFF    17480
#define WB_OFF    17648
#define SMEM_FLOATS 17816   // 71264 B

// Three CTAs per (b,p) plane: all compute the full plane (duplicated, cheap),
// each stores only its third of every output. grid = 48*3 = 144 (~1 CTA/SM).
// Thirds are warp-aligned: part 0 -> cells [0,352), part 1 -> [352,704),
// part 2 -> [704,1024) (11/11/10 warps).

__global__ __launch_bounds__(1024, 1) void rwr_kernel(
    const float* __restrict__ X,
    const int*   __restrict__ TE,
    const float* __restrict__ Wt,   // (1192, 8)
    const float* __restrict__ Wr,   // (1192, 1)
    const float* __restrict__ Wb,   // (1192, 1)
    float*       __restrict__ out)
{
    extern __shared__ __align__(16) float sm[];
    float* tp    = sm + TP_OFF;     // tp[d*1156 + r*34 + c]
    float* xs    = sm + XS_OFF;     // xs[buf*1156 + r*34 + c]
    float* stage = sm + STG_OFF;
    float* wte_s = sm + WTE_OFF;
    float* wr_s  = sm + WR_OFF;
    float* wb_s  = sm + WB_OFF;

    const int bp   = blockIdx.x / 3;    // 0..47
    const int part = blockIdx.x % 3;    // which third of outputs this CTA owns
    const int b    = bp / PP;
    const int p    = bp % PP;
    const int cell = threadIdx.x;       // 0..1023
    const int h    = cell >> 5;
    const int w    = cell & 31;

    const int base  = part * 352;                     // 0 / 352 / 704
    const int ncell = (part == 2) ? 320 : 352;
    const bool mine = (cell >= base) && (cell < base + ncell);   // warp-uniform

    // ---- issue ALL independent global loads at cycle 0 (max MLP) ----
    const float x0 = X[bp * NUM_CELLS + cell];
    const int te_day  = TE[(b * PQ + p) * 2 + 0];
    const int te_hour = TE[(b * PQ + p) * 2 + 1];
    const int cr = TE_DEPTH + cell;

    const float4* wc4 = reinterpret_cast<const float4*>(Wt + (size_t)cr * 8);
    const float4 wc_lo = wc4[0];
    const float4 wc_hi = wc4[1];
    const float wr_c = Wr[cr];
    const float wb_c = Wb[cr];

    // speculative te-block load -> smem (independent of TE value):
    //  Wt[0:168] = 336 float4; Wr[0:168] = 42 float4; Wb[0:168] = 42 float4
    if (cell < 420) {
        float4 v;
        if (cell < 336)      v = reinterpret_cast<const float4*>(Wt)[cell];
        else if (cell < 378) v = reinterpret_cast<const float4*>(Wr)[cell - 336];
        else                 v = reinterpret_cast<const float4*>(Wb)[cell - 378];
        float4* dst;
        if (cell < 336)      dst = reinterpret_cast<float4*>(wte_s) + cell;
        else if (cell < 378) dst = reinterpret_cast<float4*>(wr_s) + (cell - 336);
        else                 dst = reinterpret_cast<float4*>(wb_s) + (cell - 378);
        *dst = v;
    }

    // ---- full float4 zero of tp + xs (2890 float4); interior refilled after BAR#1 ----
    {
        float4* z4 = reinterpret_cast<float4*>(sm);
        const float4 zv = make_float4(0.f, 0.f, 0.f, 0.f);
        z4[cell] = zv;
        z4[cell + 1024] = zv;
        if (cell < 842) z4[cell + 2048] = zv;
    }

    __syncthreads();   // BAR#1: te-block resident + zero done

    // ---- read te row from smem (no second DRAM trip) ----
    const int te = te_day * 24 + te_hour;            // < 168
    const float4 wt_lo = reinterpret_cast<const float4*>(wte_s)[te * 2];
    const float4 wt_hi = reinterpret_cast<const float4*>(wte_s)[te * 2 + 1];
    const float wr_te = wr_s[te];
    const float wb_te = wb_s[te];

    // ---- softmax over 8 dirs (fast math; logits tiny, skip max-sub) ----
    float e[8], s = 0.f;
    e[0] = __expf(wt_lo.x + wc_lo.x);  e[1] = __expf(wt_lo.y + wc_lo.y);
    e[2] = __expf(wt_lo.z + wc_lo.z);  e[3] = __expf(wt_lo.w + wc_lo.w);
    e[4] = __expf(wt_hi.x + wc_hi.x);  e[5] = __expf(wt_hi.y + wc_hi.y);
    e[6] = __expf(wt_hi.z + wc_hi.z);  e[7] = __expf(wt_hi.w + wc_hi.w);
    #pragma unroll
    for (int d = 0; d < 8; d++) s += e[d];
    const float inv_s = __fdividef(1.0f, s);
    float tpv[8];
    #pragma unroll
    for (int d = 0; d < 8; d++) tpv[d] = e[d] * inv_s;

    const float rz = wr_te + wr_c;
    const float restart = __fdividef(1.0f, 1.0f + __expf(-rz));
    const float one_m_r = 1.0f - restart;
    const float bias = (wb_te + wb_c) * x0;

    // ---- static outputs: ONLY this CTA's third ----
    if (mine) {
        float4* t4 = reinterpret_cast<float4*>(out + OFF_T + (size_t)(bp * NUM_CELLS + cell) * 8);
        t4[0] = make_float4(tpv[0], tpv[1], tpv[2], tpv[3]);
        t4[1] = make_float4(tpv[4], tpv[5], tpv[6], tpv[7]);
        out[OFF_R + bp * NUM_CELLS + cell] = restart;
    }

    // ---- fill tp interior + x0 into xs buf0 + stage[0] (all pre-BAR#2) ----
    const int ctr = (h + 1) * 34 + (w + 1);
    #pragma unroll
    for (int d = 0; d < 8; d++) tp[d * 1156 + ctr] = tpv[d];

    float* const xc0 = xs + ctr;          // buf 0 center
    float* const xc1 = xs + 1156 + ctr;   // buf 1 center
    float* sp = stage + (cell - base) * 13;   // per-cell stage pointer (local third)

    xc0[0] = x0;
    if (mine) sp[0] = x0;

    __syncthreads();   // BAR#2: tp + xs buf0 ready

    // DIRS d: 0:(-1,-1) 1:(-1,0) 2:(-1,1) 3:(0,-1) 4:(0,1) 5:(1,-1) 6:(1,0) 7:(1,1)
    float w_in[8];
    {
        const float* tpc = tp + ctr;
        w_in[0] = tpc[0 * 1156 - 35];
        w_in[1] = tpc[1 * 1156 - 34];
        w_in[2] = tpc[2 * 1156 - 33];
        w_in[3] = tpc[3 * 1156 -  1];
        w_in[4] = tpc[4 * 1156 +  1];
        w_in[5] = tpc[5 * 1156 + 33];
        w_in[6] = tpc[6 * 1156 + 34];
        w_in[7] = tpc[7 * 1156 + 35];
    }

    // ---- peeled iteration 0 (reads buf0, covered by BAR#2) ----
    float x;
    {
        float a0 = xc0[-35] * w_in[0];
        float a1 = xc0[-34] * w_in[1];
        float a2 = xc0[-33] * w_in[2];
        float a3 = xc0[ -1] * w_in[3];
        a0 = fmaf(xc0[  1], w_in[4], a0);
        a1 = fmaf(xc0[ 33], w_in[5], a1);
        a2 = fmaf(xc0[ 34], w_in[6], a2);
        a3 = fmaf(xc0[ 35], w_in[7], a3);
        const float xt = (a0 + a1) + (a2 + a3);
        x = fmaf(one_m_r, xt, fmaf(restart, x0, bias));
        if (mine) sp[1] = x;
    }

    // ---- iterations 1..11: store -> BAR -> stencil ----
    #pragma unroll
    for (int k = 1; k < KSTEP; k++) {
        float* const xb = (k & 1) ? xc1 : xc0;
        xb[0] = x;
        __syncthreads();
        float a0 = xb[-35] * w_in[0];
        float a1 = xb[-34] * w_in[1];
        float a2 = xb[-33] * w_in[2];
        float a3 = xb[ -1] * w_in[3];
        a0 = fmaf(xb[  1], w_in[4], a0);
        a1 = fmaf(xb[ 33], w_in[5], a1);
        a2 = fmaf(xb[ 34], w_in[6], a2);
        a3 = fmaf(xb[ 35], w_in[7], a3);
        const float xt = (a0 + a1) + (a2 + a3);
        x = fmaf(one_m_r, xt, fmaf(restart, x, bias));
        if (mine) sp[k + 1] = x;
    }

    // final state x + Y: only this CTA's third
    if (mine) {
        out[OFF_X + bp * NUM_CELLS + cell] = x;
        if (p == PP - 1)
            out[OFF_Y + b * NUM_CELLS + cell] = x;
    }

    // ---- one barrier, then dump ONLY this third (1144 / 1144 / 1040 float4) ----
    __syncthreads();
    const int n4 = (ncell * 13) >> 2;          // 1144 or 1040
    const float4* s4 = reinterpret_cast<const float4*>(stage);
    float4* o4 = reinterpret_cast<float4*>(out + OFF_RES + (size_t)bp * (NUM_CELLS * 13))
                 + ((base * 13) >> 2);
    o4[cell] = s4[cell];                       // cell < 1024 <= n4? (1024 < 1144 ok; part2: 1024<1040 ok)
    if (cell < n4 - 1024) o4[cell + 1024] = s4[cell + 1024];
}

extern "C" void kernel_launch(void* const* d_in, const int* in_sizes, int n_in,
                              void* d_out, int out_size) {
    const float* X  = (const float*)d_in[0];
    const int*   TE = (const int*)d_in[1];
    const float* Wt = (const float*)d_in[2];
    const float* Wr = (const float*)d_in[3];
    const float* Wb = (const float*)d_in[4];
    float* out = (float*)d_out;
    const int smem_bytes = SMEM_FLOATS * 4;   // 71264 B
    cudaFuncSetAttribute(rwr_kernel, cudaFuncAttributeMaxDynamicSharedMemorySize, smem_bytes);
    rwr_kernel<<<BB * PP * 3, 1024, smem_bytes>>>(X, TE, Wt, Wr, Wb, out);
}